// round 5
// baseline (speedup 1.0000x reference)
#include <cuda_runtime.h>

// out[b,i,d] = x[b,i] * W[i,d] + b[i,d]
// B=128, N=1024, D=512 fp32. Pure HBM-write-bound: 268MB out, 4.5MB in.
//
// R3: back to the R1 multi-wave layout (it won), but tuned for occupancy:
//   - B_PER_BLOCK 16 -> 8 halves the xs[] prefetch + address registers
//   - __launch_bounds__(128, 12) caps regs (~42) -> up to 48 warps/SM
//   - more CTAs (16384) + more warps/SM = deeper outstanding-store queue,
//     which is what actually drives DRAM write duty cycle (R2 lesson).

#define BB 128
#define NN 1024
#define DD 512
#define D4 (DD / 4)          // 128 float4 per row == blockDim
#define B_PER_BLOCK 8

__global__ __launch_bounds__(D4, 12)
void fused_scalar_linear_kernel(const float* __restrict__ x,
                                const float4* __restrict__ W,
                                const float4* __restrict__ bias,
                                float4* __restrict__ out) {
    const int i  = blockIdx.x;       // neuron row 0..NN-1
    const int bc = blockIdx.y;       // batch chunk 0..BB/B_PER_BLOCK-1
    const int d4 = threadIdx.x;      // 0..D4-1

    // One-time register load of this thread's W/b slice.
    const float4 w  = W[i * D4 + d4];
    const float4 bv = bias[i * D4 + d4];

    const int b0 = bc * B_PER_BLOCK;

    // Prefetch the chunk's x scalars (broadcast loads, independent -> MLP).
    float xs[B_PER_BLOCK];
    #pragma unroll
    for (int k = 0; k < B_PER_BLOCK; ++k) {
        xs[k] = __ldg(&x[(size_t)(b0 + k) * NN + i]);
    }

    float4* __restrict__ o_base = out + (size_t)i * D4 + d4;

    #pragma unroll
    for (int k = 0; k < B_PER_BLOCK; ++k) {
        float4 o;
        o.x = fmaf(xs[k], w.x, bv.x);
        o.y = fmaf(xs[k], w.y, bv.y);
        o.z = fmaf(xs[k], w.z, bv.z);
        o.w = fmaf(xs[k], w.w, bv.w);
        // 128 threads x 16B = 2KB contiguous row store, fully coalesced.
        o_base[(size_t)(b0 + k) * (NN * D4)] = o;
    }
}

extern "C" void kernel_launch(void* const* d_in, const int* in_sizes, int n_in,
                              void* d_out, int out_size) {
    const float*  x    = (const float*)d_in[0];   // [B, N, 1]
    const float4* W    = (const float4*)d_in[1];  // [N, D]
    const float4* bias = (const float4*)d_in[2];  // [N, D]
    float4* out = (float4*)d_out;                 // [B, N, D]

    dim3 grid(NN, BB / B_PER_BLOCK);
    fused_scalar_linear_kernel<<<grid, D4>>>(x, W, bias, out);
}

// round 6
// speedup vs baseline: 1.4981x; 1.4981x over previous
#include <cuda_runtime.h>

// out[b,i,d] = x[b,i] * W[i,d] + b[i,d]
// B=128, N=1024, D=512 fp32. Pure HBM-write-bound: 268MB out, 4.5MB in.
//
// R4 = R1 (best known: B_PER_BLOCK=16, bounds(128,8)) + __stcs streaming
// stores. Single-variable change: evict-first output lines -> immediate,
// smooth dirty-line writeback; W/b (4MB) stays L2-resident. Targets
// sustained DRAM write BW, which R3's post-mortem identified as the
// true limiter (kernel retires before L2 drains).

#define BB 128
#define NN 1024
#define DD 512
#define D4 (DD / 4)          // 128 float4 per row == blockDim
#define B_PER_BLOCK 16

__global__ __launch_bounds__(D4, 8)
void fused_scalar_linear_kernel(const float* __restrict__ x,
                                const float4* __restrict__ W,
                                const float4* __restrict__ bias,
                                float4* __restrict__ out) {
    const int i  = blockIdx.x;       // neuron row 0..NN-1
    const int bc = blockIdx.y;       // batch chunk 0..BB/B_PER_BLOCK-1
    const int d4 = threadIdx.x;      // 0..D4-1

    // One-time register load of this thread's W/b slice.
    const float4 w  = W[i * D4 + d4];
    const float4 bv = bias[i * D4 + d4];

    const int b0 = bc * B_PER_BLOCK;

    // Prefetch all x scalars for the chunk up front (independent LDGs -> MLP).
    float xs[B_PER_BLOCK];
    #pragma unroll
    for (int k = 0; k < B_PER_BLOCK; ++k) {
        xs[k] = __ldg(&x[(size_t)(b0 + k) * NN + i]);
    }

    float4* __restrict__ o_base = out + (size_t)i * D4 + d4;

    #pragma unroll
    for (int k = 0; k < B_PER_BLOCK; ++k) {
        float4 o;
        o.x = fmaf(xs[k], w.x, bv.x);
        o.y = fmaf(xs[k], w.y, bv.y);
        o.z = fmaf(xs[k], w.z, bv.z);
        o.w = fmaf(xs[k], w.w, bv.w);
        // Streaming (evict-first) store: 2KB contiguous per CTA row,
        // dirty lines written back to DRAM immediately.
        __stcs(o_base + (size_t)(b0 + k) * (NN * D4), o);
    }
}

extern "C" void kernel_launch(void* const* d_in, const int* in_sizes, int n_in,
                              void* d_out, int out_size) {
    const float*  x    = (const float*)d_in[0];   // [B, N, 1]
    const float4* W    = (const float4*)d_in[1];  // [N, D]
    const float4* bias = (const float4*)d_in[2];  // [N, D]
    float4* out = (float4*)d_out;                 // [B, N, D]

    dim3 grid(NN, BB / B_PER_BLOCK);
    fused_scalar_linear_kernel<<<grid, D4>>>(x, W, bias, out);
}